// round 10
// baseline (speedup 1.0000x reference)
#include <cuda_runtime.h>
#include <cstdint>
#include <cstddef>
#include <cstring>

#define NTIME 20
#define V     128
#define F     128
#define LRELU_ALPHA 0.2f
#define LOG2E 1.4426950408889634f

#define OUT_HP_ELEMS   (NTIME * V * F)
#define ATT_OFF        OUT_HP_ELEMS

__device__ float g_Wh[NTIME * V * F];
__device__ float g_C1[F * F];            // (W @ a1) * LOG2E
__device__ float g_C2[F * F];            // (W @ a2) * LOG2E
__device__ float g_P1[NTIME * V * F];    // exp2(l*e1)
__device__ float g_N1[NTIME * V * F];    // exp2(0.2*l*e1)
__device__ float g_PN2[NTIME * V * F * 2]; // interleaved (exp2(l*e2), exp2(0.2*l*e2))

__device__ __forceinline__ float ex2(float x) {
    float r; asm("ex2.approx.f32 %0, %1;" : "=f"(r) : "f"(x)); return r;
}

// ----------------------------------------------------------------------------
// gemm tile: 256 threads, MT=8 rows, 4 rows/thread (high block count for occ).
// ----------------------------------------------------------------------------
#define MT 8

__device__ __forceinline__ void gemm_tile(
    const float* __restrict__ smtile,   // [MT][F]
    const float* __restrict__ M,        // [F][F]
    float acc[4], int f, int half)
{
#pragma unroll 8
    for (int k4 = 0; k4 < F / 4; k4++) {
        float mv[4];
#pragma unroll
        for (int u = 0; u < 4; u++)
            mv[u] = __ldg(M + (k4 * 4 + u) * F + f);
#pragma unroll
        for (int r = 0; r < 4; r++) {
            const float4 hv = ((const float4*)(smtile + (half * 4 + r) * F))[k4];
            acc[r] = fmaf(hv.x, mv[0], acc[r]);
            acc[r] = fmaf(hv.y, mv[1], acc[r]);
            acc[r] = fmaf(hv.z, mv[2], acc[r]);
            acc[r] = fmaf(hv.w, mv[3], acc[r]);
        }
    }
}

// ----------------------------------------------------------------------------
// Kernel A: blocks [0,320): Wh = h @ W (MT=8)
//           blocks [320,576): split-K C{1,2} = (W @ a{1,2}) * LOG2E
// ----------------------------------------------------------------------------
__global__ void __launch_bounds__(256) gemmA(
    const float* __restrict__ h,
    const float* __restrict__ W,
    const float* __restrict__ a)
{
    __shared__ float smem[MT * F];   // Wh: h tile (4KB); prep: wrow[128]+red[256]

    const int tid  = threadIdx.x;
    const int f    = tid & 127;
    const int half = tid >> 7;

    if (blockIdx.x < 320) {
        const int m0 = blockIdx.x * MT;
        ((float4*)smem)[tid] = ((const float4*)(h + (size_t)m0 * F))[tid];
        __syncthreads();

        float acc[4] = {0.f, 0.f, 0.f, 0.f};
        gemm_tile(smem, W, acc, f, half);
#pragma unroll
        for (int r = 0; r < 4; r++)
            g_Wh[(size_t)(m0 + half * 4 + r) * F + f] = acc[r];
    } else {
        float* wrow = smem;          // [128]
        float* red  = smem + 128;    // [256]
        const int idx = blockIdx.x - 320;
        const int m   = idx & 127;
        const int hh  = idx >> 7;

        if (tid < 128)
            wrow[tid] = __ldg(W + (size_t)m * F + tid);
        __syncthreads();

        const float* ap = a + (size_t)hh * F * F + half * 64 * F + f;
        float acc = 0.0f;
#pragma unroll
        for (int u = 0; u < 64; u++)
            acc = fmaf(wrow[half * 64 + u], __ldg(ap + u * F), acc);

        red[tid] = acc;
        __syncthreads();

        if (half == 0) {
            float* dst = hh ? g_C2 : g_C1;
            dst[(size_t)m * F + f] = (red[f] + red[f + 128]) * LOG2E;
        }
    }
}

// ----------------------------------------------------------------------------
// Kernel B: acc = h @ C{1,2}  (= log2e * e{1,2}), epilogue writes exp tables:
//   by=0: g_P1 = ex2(acc), g_N1 = ex2(0.2*acc)
//   by=1: g_PN2 interleaved (ex2(acc), ex2(0.2*acc))
// grid (320, 2), 256 threads, MT=8.
// ----------------------------------------------------------------------------
__global__ void __launch_bounds__(256) gemmB(const float* __restrict__ h)
{
    __shared__ float hs[MT * F];
    const int tid  = threadIdx.x;
    const int f    = tid & 127;
    const int half = tid >> 7;
    const int m0   = blockIdx.x * MT;
    const int by   = blockIdx.y;

    ((float4*)hs)[tid] = ((const float4*)(h + (size_t)m0 * F))[tid];
    __syncthreads();

    float acc[4] = {0.f, 0.f, 0.f, 0.f};
    gemm_tile(hs, by ? g_C2 : g_C1, acc, f, half);

#pragma unroll
    for (int r = 0; r < 4; r++) {
        const size_t idx = (size_t)(m0 + half * 4 + r) * F + f;
        const float P = ex2(acc[r]);
        const float N = ex2(LRELU_ALPHA * acc[r]);
        if (by == 0) {
            g_P1[idx] = P;
            g_N1[idx] = N;
        } else {
            *(float2*)(g_PN2 + idx * 2) = make_float2(P, N);
        }
    }
}

// ----------------------------------------------------------------------------
// Kernel C: attention with PRODUCT-FORM exp (zero MUFU in hot loop):
//   p = (P1*P2 > 1) ? P1*P2 : N1*N2
// j-split layout from R7: two warps per (i, f-half), each owning 64 j's;
// partials exchanged via smem. smem = PN2 tile 64KB + red 8KB = 72KB, 3 CTA/SM.
// Wh read via LDG (L2-resident) in pass A only.
// ----------------------------------------------------------------------------
#define FH  64
#define IPB 8
#define ATTN_SMEM_BYTES ((2 * V * FH + 16 * 32 * 4) * (int)sizeof(float))

__global__ void __launch_bounds__(512, 3) attn_fused(
    const float* __restrict__ adj,
    float* __restrict__ out)
{
    extern __shared__ float sm[];
    float*  pn2 = sm;                        // [V][FH][2] = (P2,N2) interleaved
    float4* red = (float4*)(sm + 2 * V * FH);

    const int t    = blockIdx.y;
    const int bx   = blockIdx.x;      // 0..31
    const int fh   = bx & 1;
    const int ig   = bx >> 1;         // 0..15
    const int tid  = threadIdx.x;
    const int lane = tid & 31;
    const int w    = tid >> 5;        // warp 0..15
    const int il   = w >> 1;          // local i 0..7
    const int jh   = w & 1;           // j-half
    const int i    = ig * IPB + il;
    const int f2   = fh * FH + lane * 2;

    uint32_t bits[2];
    {
        const float* arow = adj + (size_t)i * V + jh * 64;
        bits[0] = __ballot_sync(0xFFFFFFFFu, arow[lane]      > 0.0f);
        bits[1] = __ballot_sync(0xFFFFFFFFu, arow[32 + lane] > 0.0f);
    }

    // coop load PN2 tile: V rows x (FH*2 floats) = 4096 float4, 8 per thread
    {
        const float* src = g_PN2 + ((size_t)t * V * F + fh * FH) * 2;
#pragma unroll
        for (int u = 0; u < 8; u++) {
            const int idx = tid + u * 512;     // 0..4095
            const int j = idx >> 5, c = idx & 31;
            ((float4*)pn2)[idx] = *(const float4*)(src + (size_t)j * F * 2 + c * 4);
        }
    }

    const float2 p1 = *(const float2*)(g_P1 + ((size_t)t * V + i) * F + f2);
    const float2 n1 = *(const float2*)(g_N1 + ((size_t)t * V + i) * F + f2);
    __syncthreads();

    const float* pnl = pn2 + (jh * 64) * FH * 2 + lane * 4;
    const float* whg = g_Wh + ((size_t)t * V + jh * 64) * F + f2;

    // Pass A: partial sums over own 64 j's
    float s0 = 0.0f, s1 = 0.0f, a0 = 0.0f, a1 = 0.0f;
#pragma unroll
    for (int ww = 0; ww < 2; ww++) {
        const uint32_t bw = bits[ww];
        const float* pnw = pnl + ww * 32 * FH * 2;
        const float* whw = whg + (size_t)ww * 32 * F;
#pragma unroll
        for (int b = 0; b < 32; b++) {
            if (bw & (1u << b)) {
                const float4 q  = *(const float4*)(pnw + b * FH * 2); // P2a,N2a,P2b,N2b
                const float2 wv = __ldg((const float2*)(whw + (size_t)b * F));
                const float pp0 = p1.x * q.x, pn0 = n1.x * q.y;
                const float pp1 = p1.y * q.z, pn1 = n1.y * q.w;
                const float v0 = (pp0 > 1.0f) ? pp0 : pn0;
                const float v1 = (pp1 > 1.0f) ? pp1 : pn1;
                s0 += v0;  s1 += v1;
                a0 = fmaf(v0, wv.x, a0);
                a1 = fmaf(v1, wv.y, a1);
            }
        }
    }

    red[w * 32 + lane] = make_float4(s0, s1, a0, a1);
    __syncthreads();
    {
        const float4 o = red[(w ^ 1) * 32 + lane];
        s0 += o.x; s1 += o.y; a0 += o.z; a1 += o.w;
    }

    const float r0 = 1.0f / s0;
    const float r1 = 1.0f / s1;

    if (jh == 0) {
        const float hp0 = a0 * r0;
        const float hp1 = a1 * r1;
        float2 o;
        o.x = (hp0 > 0.0f) ? hp0 : expm1f(hp0);
        o.y = (hp1 > 0.0f) ? hp1 : expm1f(hp1);
        *(float2*)(out + ((size_t)t * V + i) * F + f2) = o;
    }

    // Pass B: prescaled products, stream normalized attention
    const float P1ra = p1.x * r0, N1ra = n1.x * r0;
    const float P1rb = p1.y * r1, N1rb = n1.y * r1;

    float* ab = out + ATT_OFF + (((size_t)t * V + i) * V + jh * 64) * F + f2;
#pragma unroll
    for (int ww = 0; ww < 2; ww++) {
        const uint32_t bw = bits[ww];
        const float* pnw = pnl + ww * 32 * FH * 2;
        float* abw = ab + (size_t)ww * 32 * F;
#pragma unroll
        for (int b = 0; b < 32; b++) {
            float2 pv;
            if (bw & (1u << b)) {
                const float4 q = *(const float4*)(pnw + b * FH * 2);
                const float pp0 = P1ra * q.x, pn0 = N1ra * q.y;
                const float pp1 = P1rb * q.z, pn1 = N1rb * q.w;
                pv.x = (pp0 > r0) ? pp0 : pn0;
                pv.y = (pp1 > r1) ? pp1 : pn1;
            } else {
                pv.x = 0.0f; pv.y = 0.0f;
            }
            __stcs((float2*)(abw + b * F), pv);
        }
    }
}

// ----------------------------------------------------------------------------
extern "C" void kernel_launch(void* const* d_in, const int* in_sizes, int n_in,
                              void* d_out, int out_size)
{
    const float* h   = (const float*)d_in[0];   // [2560,128]
    const float* adj = (const float*)d_in[1];   // [128,128,1]
    const float* W   = (const float*)d_in[2];   // [128,128]
    const float* a   = (const float*)d_in[3];   // [256,128]
    float* out = (float*)d_out;

    cudaFuncSetAttribute(attn_fused, cudaFuncAttributeMaxDynamicSharedMemorySize,
                         ATTN_SMEM_BYTES);

    gemmA<<<576, 256>>>(h, W, a);

    dim3 g1(320, 2);
    gemmB<<<g1, 256>>>(h);

    dim3 g2(32, NTIME);
    attn_fused<<<g2, 512, ATTN_SMEM_BYTES>>>(adj, out);
}

// round 11
// speedup vs baseline: 1.0470x; 1.0470x over previous
#include <cuda_runtime.h>
#include <cstdint>
#include <cstddef>
#include <cstring>

#define NTIME 20
#define V     128
#define F     128
#define LRELU_ALPHA 0.2f
#define LOG2E 1.4426950408889634f
#define ALOG2E (LRELU_ALPHA * LOG2E)

#define OUT_HP_ELEMS   (NTIME * V * F)
#define ATT_OFF        OUT_HP_ELEMS

__device__ float g_Wh[NTIME * V * F];
__device__ float g_P1[NTIME * V * F];      // exp2(log2e * e1)
__device__ float g_N1[NTIME * V * F];      // exp2(0.2 * log2e * e1)
__device__ float g_PN2[NTIME * V * F * 2]; // interleaved (exp2(l*e2), exp2(0.2l*e2))

__device__ __forceinline__ float ex2(float x) {
    float r; asm("ex2.approx.f32 %0, %1;" : "=f"(r) : "f"(x)); return r;
}

// ----------------------------------------------------------------------------
// Kernel 1 (fused): per block of MT=8 rows:
//   phase 1: Wh = h @ W        -> smem whs + g_Wh
//   phase 2: e1 = Whs @ a1, e2 = Whs @ a2  -> ex2 tables (P1/N1, PN2)
// 256 threads: f = tid&127, half = tid>>7, 4 rows/thread. grid = 320.
// W (64KB) + a (128KB) stay L1-resident across phases/blocks.
// ----------------------------------------------------------------------------
#define MT 8

__global__ void __launch_bounds__(256) gemm_fused(
    const float* __restrict__ h,
    const float* __restrict__ W,
    const float* __restrict__ a)
{
    __shared__ float hs[MT * F];
    __shared__ float whs[MT * F];

    const int tid  = threadIdx.x;
    const int f    = tid & 127;
    const int half = tid >> 7;
    const int m0   = blockIdx.x * MT;

    ((float4*)hs)[tid] = ((const float4*)(h + (size_t)m0 * F))[tid];
    __syncthreads();

    // ---- phase 1: Wh ----
    {
        float acc[4] = {0.f, 0.f, 0.f, 0.f};
#pragma unroll 8
        for (int k4 = 0; k4 < F / 4; k4++) {
            float mv[4];
#pragma unroll
            for (int u = 0; u < 4; u++)
                mv[u] = __ldg(W + (k4 * 4 + u) * F + f);
#pragma unroll
            for (int r = 0; r < 4; r++) {
                const float4 hv = ((const float4*)(hs + (half * 4 + r) * F))[k4];
                acc[r] = fmaf(hv.x, mv[0], acc[r]);
                acc[r] = fmaf(hv.y, mv[1], acc[r]);
                acc[r] = fmaf(hv.z, mv[2], acc[r]);
                acc[r] = fmaf(hv.w, mv[3], acc[r]);
            }
        }
#pragma unroll
        for (int r = 0; r < 4; r++) {
            const int row = half * 4 + r;
            whs[row * F + f] = acc[r];
            g_Wh[(size_t)(m0 + row) * F + f] = acc[r];
        }
    }
    __syncthreads();

    // ---- phase 2: e1, e2 from whs ----
    {
        float ac1[4] = {0.f, 0.f, 0.f, 0.f};
        float ac2[4] = {0.f, 0.f, 0.f, 0.f};
#pragma unroll 8
        for (int k4 = 0; k4 < F / 4; k4++) {
            float a1v[4], a2v[4];
#pragma unroll
            for (int u = 0; u < 4; u++) {
                a1v[u] = __ldg(a + (k4 * 4 + u) * F + f);
                a2v[u] = __ldg(a + (F + k4 * 4 + u) * F + f);
            }
#pragma unroll
            for (int r = 0; r < 4; r++) {
                const float4 wv = ((const float4*)(whs + (half * 4 + r) * F))[k4];
                ac1[r] = fmaf(wv.x, a1v[0], ac1[r]);
                ac1[r] = fmaf(wv.y, a1v[1], ac1[r]);
                ac1[r] = fmaf(wv.z, a1v[2], ac1[r]);
                ac1[r] = fmaf(wv.w, a1v[3], ac1[r]);
                ac2[r] = fmaf(wv.x, a2v[0], ac2[r]);
                ac2[r] = fmaf(wv.y, a2v[1], ac2[r]);
                ac2[r] = fmaf(wv.z, a2v[2], ac2[r]);
                ac2[r] = fmaf(wv.w, a2v[3], ac2[r]);
            }
        }
#pragma unroll
        for (int r = 0; r < 4; r++) {
            const size_t idx = (size_t)(m0 + half * 4 + r) * F + f;
            g_P1[idx] = ex2(LOG2E  * ac1[r]);
            g_N1[idx] = ex2(ALOG2E * ac1[r]);
            *(float2*)(g_PN2 + idx * 2) =
                make_float2(ex2(LOG2E * ac2[r]), ex2(ALOG2E * ac2[r]));
        }
    }
}

// ----------------------------------------------------------------------------
// Kernel 2: attention with product-form exp (zero MUFU in hot loop):
//   p = (P1*P2 > 1) ? P1*P2 : N1*N2
// j-split: two warps per (i, f-half), each owning 64 j's; partials via smem.
// Block = 512 threads, grid = 32 x 20, smem 72KB, 3 CTA/SM.
// ----------------------------------------------------------------------------
#define FH  64
#define IPB 8
#define ATTN_SMEM_BYTES ((2 * V * FH + 16 * 32 * 4) * (int)sizeof(float))

__global__ void __launch_bounds__(512, 3) attn_fused(
    const float* __restrict__ adj,
    float* __restrict__ out)
{
    extern __shared__ float sm[];
    float*  pn2 = sm;                        // [V][FH][2] = (P2,N2) interleaved
    float4* red = (float4*)(sm + 2 * V * FH);

    const int t    = blockIdx.y;
    const int bx   = blockIdx.x;      // 0..31
    const int fh   = bx & 1;
    const int ig   = bx >> 1;         // 0..15
    const int tid  = threadIdx.x;
    const int lane = tid & 31;
    const int w    = tid >> 5;        // warp 0..15
    const int il   = w >> 1;          // local i 0..7
    const int jh   = w & 1;           // j-half
    const int i    = ig * IPB + il;
    const int f2   = fh * FH + lane * 2;

    uint32_t bits[2];
    {
        const float* arow = adj + (size_t)i * V + jh * 64;
        bits[0] = __ballot_sync(0xFFFFFFFFu, arow[lane]      > 0.0f);
        bits[1] = __ballot_sync(0xFFFFFFFFu, arow[32 + lane] > 0.0f);
    }

    // coop load PN2 tile: 4096 float4, 8 per thread
    {
        const float* src = g_PN2 + ((size_t)t * V * F + fh * FH) * 2;
#pragma unroll
        for (int u = 0; u < 8; u++) {
            const int idx = tid + u * 512;     // 0..4095
            const int j = idx >> 5, c = idx & 31;
            ((float4*)pn2)[idx] = *(const float4*)(src + (size_t)j * F * 2 + c * 4);
        }
    }

    const float2 p1 = *(const float2*)(g_P1 + ((size_t)t * V + i) * F + f2);
    const float2 n1 = *(const float2*)(g_N1 + ((size_t)t * V + i) * F + f2);
    __syncthreads();

    const float* pnl = pn2 + (jh * 64) * FH * 2 + lane * 4;
    const float* whg = g_Wh + ((size_t)t * V + jh * 64) * F + f2;

    // Pass A: partial sums over own 64 j's
    float s0 = 0.0f, s1 = 0.0f, a0 = 0.0f, a1 = 0.0f;
#pragma unroll
    for (int ww = 0; ww < 2; ww++) {
        const uint32_t bw = bits[ww];
        const float* pnw = pnl + ww * 32 * FH * 2;
        const float* whw = whg + (size_t)ww * 32 * F;
#pragma unroll
        for (int b = 0; b < 32; b++) {
            if (bw & (1u << b)) {
                const float4 q  = *(const float4*)(pnw + b * FH * 2);
                const float2 wv = __ldg((const float2*)(whw + (size_t)b * F));
                const float pp0 = p1.x * q.x, pn0 = n1.x * q.y;
                const float pp1 = p1.y * q.z, pn1 = n1.y * q.w;
                const float v0 = (pp0 > 1.0f) ? pp0 : pn0;
                const float v1 = (pp1 > 1.0f) ? pp1 : pn1;
                s0 += v0;  s1 += v1;
                a0 = fmaf(v0, wv.x, a0);
                a1 = fmaf(v1, wv.y, a1);
            }
        }
    }

    red[w * 32 + lane] = make_float4(s0, s1, a0, a1);
    __syncthreads();
    {
        const float4 o = red[(w ^ 1) * 32 + lane];
        s0 += o.x; s1 += o.y; a0 += o.z; a1 += o.w;
    }

    const float r0 = 1.0f / s0;
    const float r1 = 1.0f / s1;

    if (jh == 0) {
        const float hp0 = a0 * r0;
        const float hp1 = a1 * r1;
        float2 o;
        o.x = (hp0 > 0.0f) ? hp0 : expm1f(hp0);
        o.y = (hp1 > 0.0f) ? hp1 : expm1f(hp1);
        *(float2*)(out + ((size_t)t * V + i) * F + f2) = o;
    }

    // Pass B: prescaled products, stream normalized attention
    const float P1ra = p1.x * r0, N1ra = n1.x * r0;
    const float P1rb = p1.y * r1, N1rb = n1.y * r1;

    float* ab = out + ATT_OFF + (((size_t)t * V + i) * V + jh * 64) * F + f2;
#pragma unroll
    for (int ww = 0; ww < 2; ww++) {
        const uint32_t bw = bits[ww];
        const float* pnw = pnl + ww * 32 * FH * 2;
        float* abw = ab + (size_t)ww * 32 * F;
#pragma unroll
        for (int b = 0; b < 32; b++) {
            float2 pv;
            if (bw & (1u << b)) {
                const float4 q = *(const float4*)(pnw + b * FH * 2);
                const float pp0 = P1ra * q.x, pn0 = N1ra * q.y;
                const float pp1 = P1rb * q.z, pn1 = N1rb * q.w;
                pv.x = (pp0 > r0) ? pp0 : pn0;
                pv.y = (pp1 > r1) ? pp1 : pn1;
            } else {
                pv.x = 0.0f; pv.y = 0.0f;
            }
            __stcs((float2*)(abw + b * F), pv);
        }
    }
}

// ----------------------------------------------------------------------------
extern "C" void kernel_launch(void* const* d_in, const int* in_sizes, int n_in,
                              void* d_out, int out_size)
{
    const float* h   = (const float*)d_in[0];   // [2560,128]
    const float* adj = (const float*)d_in[1];   // [128,128,1]
    const float* W   = (const float*)d_in[2];   // [128,128]
    const float* a   = (const float*)d_in[3];   // [256,128]
    float* out = (float*)d_out;

    cudaFuncSetAttribute(attn_fused, cudaFuncAttributeMaxDynamicSharedMemorySize,
                         ATTN_SMEM_BYTES);

    gemm_fused<<<320, 256>>>(h, W, a);

    dim3 g2(32, NTIME);
    attn_fused<<<g2, 512, ATTN_SMEM_BYTES>>>(adj, out);
}